// round 9
// baseline (speedup 1.0000x reference)
#include <cuda_runtime.h>

// Problem constants (fixed shapes per problem spec)
namespace {
constexpr int Bn  = 16;
constexpr int Nn  = 4096;
constexpr int Sn  = 1024;
constexpr int CPn = 64;   // point feature channels
constexpr int C3n = 128;  // final MLP out channels
constexpr int NBLK = 144; // 16 fps blocks + 128 worker blocks (<= 148 SMs)
}

// Persistent device scratch (no allocation). All sync counters are MONOTONE
// across launches/replays (never reset), so graph replay and ncu replay stay
// correct without initialization.
__device__ float    g_ptsT[(size_t)Bn * Nn * CPn];  // points (B,N,CP)
__device__ float4   g_spG[Bn * Nn];                 // (x,y,z,|p|^2) per point
__device__ float    g_H3[(size_t)Bn * Nn * C3n];    // per-point layer3 acc (pre-bias)
__device__ unsigned g_bar;                          // ticket barrier
__device__ unsigned g_progress[Bn];                 // fps centroids produced
__device__ unsigned g_tcount[Bn];                   // worker H3+tables done

// ---------------------------------------------------------------------------
// helpers
// ---------------------------------------------------------------------------
__device__ __forceinline__ unsigned long long pk2(float lo, float hi) {
    unsigned long long r;
    asm("mov.b64 %0, {%1, %2};" : "=l"(r) : "f"(lo), "f"(hi));
    return r;
}
__device__ __forceinline__ void fma2(unsigned long long& d,
                                     unsigned long long a, unsigned long long b) {
    asm("fma.rn.f32x2 %0, %1, %2, %0;" : "+l"(d) : "l"(a), "l"(b));
}
__device__ __forceinline__ unsigned long long fma2v(unsigned long long a,
                                                    unsigned long long b,
                                                    unsigned long long c) {
    unsigned long long d;
    asm("fma.rn.f32x2 %0, %1, %2, %3;" : "=l"(d) : "l"(a), "l"(b), "l"(c));
    return d;
}
__device__ __forceinline__ unsigned long long mul2(unsigned long long a,
                                                   unsigned long long b) {
    unsigned long long d;
    asm("mul.rn.f32x2 %0, %1, %2;" : "=l"(d) : "l"(a), "l"(b));
    return d;
}
__device__ __forceinline__ unsigned long long add2(unsigned long long a,
                                                   unsigned long long b) {
    unsigned long long d;
    asm("add.rn.f32x2 %0, %1, %2;" : "=l"(d) : "l"(a), "l"(b));
    return d;
}
__device__ __forceinline__ float2 up2(unsigned long long v) {
    float lo, hi;
    asm("mov.b64 {%0, %1}, %2;" : "=f"(lo), "=f"(hi) : "l"(v));
    return make_float2(lo, hi);
}
__device__ __forceinline__ unsigned acq_u32(const unsigned* p) {
    unsigned v;
    asm volatile("ld.global.acquire.gpu.u32 %0, [%1];" : "=r"(v) : "l"(p));
    return v;
}
__device__ __forceinline__ void rel_u32(unsigned* p, unsigned v) {
    asm volatile("st.global.release.gpu.u32 [%0], %1;" :: "l"(p), "r"(v) : "memory");
}
__device__ __forceinline__ float ldcg_f(const float* p) {
    float v;
    asm volatile("ld.global.cg.f32 %0, [%1];" : "=f"(v) : "l"(p));
    return v;
}

// ---------------------------------------------------------------------------
// Worker SMEM layout (floats):
//   W1t[67][64] W2t[64][64] W3t[64][128] b1 b2 b3 | knn idx (512 ints) |
//   Xt[67][ST]  H1[64][ST]
// H1 doubles as the staged kNN candidate table (4096 float4 = 65536 floats
// <= 64*ST = 66560) once H3 computation is done (H1 dead afterwards).
// ---------------------------------------------------------------------------
constexpr int ST       = 260;
constexpr int OFF_W1T  = 0;
constexpr int OFF_W2T  = OFF_W1T + 67 * 64;
constexpr int OFF_W3T  = OFF_W2T + 64 * 64;
constexpr int OFF_B1   = OFF_W3T + 64 * 128;
constexpr int OFF_B2   = OFF_B1 + 64;
constexpr int OFF_B3   = OFF_B2 + 64;
constexpr int OFF_KNN  = OFF_B3 + 128;          // 512 ints
constexpr int OFF_XT   = OFF_KNN + 512;
constexpr int OFF_H1   = OFF_XT + 67 * ST;      // 16B-aligned
constexpr int SMEM_FLOATS = OFF_H1 + 64 * ST;
constexpr int SMEM_BYTES  = SMEM_FLOATS * 4;    // 205,616 B

// One dense layer tile for 512 threads: 4 points x 8 outs per thread.
template <int C, int WS>
__device__ __forceinline__ void layer8(const float* __restrict__ Xs,
                                       const float* __restrict__ Wt,
                                       const float* __restrict__ Bs,
                                       float* __restrict__ Hs,
                                       int p0, int o0)
{
    unsigned long long acc[4][4];
#pragma unroll
    for (int i = 0; i < 4; i++)
#pragma unroll
        for (int o = 0; o < 4; o++) acc[i][o] = pk2(0.0f, 0.0f);

    for (int c = 0; c < C; c++) {
        float4 xv = *(const float4*)(Xs + c * ST + p0);
        const ulonglong2* wp = (const ulonglong2*)(Wt + c * WS + o0);
        ulonglong2 wa = wp[0], wb = wp[1];
        unsigned long long xq[4] = {pk2(xv.x, xv.x), pk2(xv.y, xv.y),
                                    pk2(xv.z, xv.z), pk2(xv.w, xv.w)};
        unsigned long long wq[4] = {wa.x, wa.y, wb.x, wb.y};
#pragma unroll
        for (int i = 0; i < 4; i++)
#pragma unroll
            for (int o = 0; o < 4; o++) fma2(acc[i][o], xq[i], wq[o]);
    }
#pragma unroll
    for (int o = 0; o < 4; o++) {
        float b0 = Bs[o0 + 2 * o], b1 = Bs[o0 + 2 * o + 1];
        float2 a0 = up2(acc[0][o]), a1 = up2(acc[1][o]);
        float2 a2 = up2(acc[2][o]), a3 = up2(acc[3][o]);
        float4 ve = make_float4(fmaxf(a0.x + b0, 0.f), fmaxf(a1.x + b0, 0.f),
                                fmaxf(a2.x + b0, 0.f), fmaxf(a3.x + b0, 0.f));
        float4 vo = make_float4(fmaxf(a0.y + b1, 0.f), fmaxf(a1.y + b1, 0.f),
                                fmaxf(a2.y + b1, 0.f), fmaxf(a3.y + b1, 0.f));
        *(float4*)(Hs + (o0 + 2 * o) * ST + p0)     = ve;
        *(float4*)(Hs + (o0 + 2 * o + 1) * ST + p0) = vo;
    }
}

// ---------------------------------------------------------------------------
// The megakernel: blocks 0..15 = FPS producers, 16..143 = workers.
// Workers: per-point MLP (H3) once for their 512-point slice, then per-chunk
// knn + max-gather pooling (the MLP depends only on the point index, so the
// per-(centroid,neighbor) recompute is redundant — 8x FLOP reduction).
// ---------------------------------------------------------------------------
__global__ __launch_bounds__(512) void sa_kernel(
    const float* __restrict__ xyz, const float* __restrict__ pts,
    const float* __restrict__ W1, const float* __restrict__ b1,
    const float* __restrict__ W2, const float* __restrict__ b2,
    const float* __restrict__ W3, const float* __restrict__ b3,
    float* out_xyz, float* out_np)
{
    extern __shared__ float sm[];
    int bx = blockIdx.x;
    int tid = threadIdx.x;
    const unsigned FULL = 0xffffffffu;

    __shared__ unsigned s_base[2];

    // read monotone bases BEFORE the rendezvous, then ticket barrier over all
    // 144 co-resident blocks
    if (tid == 0) {
        int bb = (bx < 16) ? bx : ((bx - 16) >> 3);
        s_base[0] = acq_u32(&g_progress[bb]);
        s_base[1] = acq_u32(&g_tcount[bb]);
        unsigned ticket = atomicAdd(&g_bar, 1u);
        unsigned gen = ticket / NBLK;
        while (acq_u32(&g_bar) < (gen + 1) * NBLK) __nanosleep(64);
    }
    __syncthreads();
    unsigned pbase = s_base[0];

    if (bx < 16) {
        // =================== FPS producer (identical math to R6-R8) ========
        float* sx = sm;
        float* sy = sm + Nn;
        float* sz = sm + 2 * Nn;
        unsigned* sdist = (unsigned*)(sm + 3 * Nn);
        unsigned* sidx  = sdist + 32;

        int b = bx, t = tid;
        const float* xb = xyz + (size_t)b * Nn * 3;

        unsigned long long px2[4], py2[4], pz2[4];
        float dist[8];
#pragma unroll
        for (int i = 0; i < 4; i++) {
            int j0 = t + (2 * i) * 512;
            int j1 = t + (2 * i + 1) * 512;
            float x0 = xb[3 * j0], y0 = xb[3 * j0 + 1], z0 = xb[3 * j0 + 2];
            float x1 = xb[3 * j1], y1 = xb[3 * j1 + 1], z1 = xb[3 * j1 + 2];
            px2[i] = pk2(x0, x1); py2[i] = pk2(y0, y1); pz2[i] = pk2(z0, z1);
            sx[j0] = x0; sy[j0] = y0; sz[j0] = z0;
            sx[j1] = x1; sy[j1] = y1; sz[j1] = z1;
            dist[2 * i] = 1e10f; dist[2 * i + 1] = 1e10f;
        }
        __syncthreads();

        float cx = sx[0], cy = sy[0], cz = sz[0];
        if (t == 0) {
            float* o = out_xyz + (size_t)b * Sn * 3;
            o[0] = cx; o[1] = cy; o[2] = cz;
            rel_u32(&g_progress[b], pbase + 1u);
        }

        int lane = t & 31, wd = t >> 5;
        for (int it = 1; it < Sn; ++it) {
            unsigned long long ncx2 = pk2(-cx, -cx);
            unsigned long long ncy2 = pk2(-cy, -cy);
            unsigned long long ncz2 = pk2(-cz, -cz);
#pragma unroll
            for (int i = 0; i < 4; i++) {
                unsigned long long dx = add2(px2[i], ncx2);
                unsigned long long dy = add2(py2[i], ncy2);
                unsigned long long dz = add2(pz2[i], ncz2);
                unsigned long long d2 = mul2(dx, dx);
                d2 = fma2v(dy, dy, d2);
                d2 = fma2v(dz, dz, d2);
                float2 dd = up2(d2);
                dist[2 * i]     = fminf(dist[2 * i], dd.x);
                dist[2 * i + 1] = fminf(dist[2 * i + 1], dd.y);
            }
            float mv = fmaxf(fmaxf(fmaxf(dist[0], dist[1]), fmaxf(dist[2], dist[3])),
                             fmaxf(fmaxf(dist[4], dist[5]), fmaxf(dist[6], dist[7])));
            int mi = t;
#pragma unroll
            for (int s = 7; s >= 0; s--)
                if (dist[s] == mv) mi = t + s * 512;   // lowest index wins

            unsigned db = __float_as_uint(mv);
            unsigned wm = __reduce_max_sync(FULL, db);
            unsigned ci = (db == wm) ? (unsigned)mi : 0xffffffffu;
            unsigned wi = __reduce_min_sync(FULL, ci);
            int slot = (it & 1) * 16 + wd;
            if (lane == 0) { sdist[slot] = wm; sidx[slot] = wi; }
            __syncthreads();

            int rs = (it & 1) * 16 + (lane & 15);
            unsigned d16 = sdist[rs];
            unsigned i16 = sidx[rs];
            unsigned gm  = __reduce_max_sync(FULL, d16);
            unsigned gc  = (d16 == gm) ? i16 : 0xffffffffu;
            unsigned far = __reduce_min_sync(FULL, gc);
            cx = sx[far]; cy = sy[far]; cz = sz[far];
            if (t == 0) {
                float* o = out_xyz + ((size_t)b * Sn + it) * 3;
                o[0] = cx; o[1] = cy; o[2] = cz;
                rel_u32(&g_progress[b], pbase + (unsigned)it + 1u);
            }
        }
        return;
    }

    // ======================= worker ========================================
    int b  = (bx - 16) >> 3;
    int wl = (bx - 16) & 7;
    unsigned tbase = s_base[1];

    float* sW1t = sm + OFF_W1T;
    float* sW2t = sm + OFF_W2T;
    float* sW3t = sm + OFF_W3T;
    float* sB1  = sm + OFF_B1;
    float* sB2  = sm + OFF_B2;
    float* sB3  = sm + OFF_B3;
    int*   sknn = (int*)(sm + OFF_KNN);
    float* sXt  = sm + OFF_XT;
    float* sH1  = sm + OFF_H1;
    float* sH2  = sXt;
    float4* spS = (float4*)(sm + OFF_H1);   // staged candidate table (aliases H1)

    // --- prologue: weights to smem ---
    for (int i = tid; i < 64 * 67; i += 512) { int o = i / 67, c = i % 67; sW1t[c * 64 + o] = W1[i]; }
    for (int i = tid; i < 64 * 64; i += 512) { int o = i >> 6, c = i & 63; sW2t[c * 64 + o] = W2[i]; }
    for (int i = tid; i < 128 * 64; i += 512){ int o = i >> 6, c = i & 63; sW3t[c * 128 + o] = W3[i]; }
    if (tid < 64)  sB1[tid] = b1[tid];
    if (tid < 64)  sB2[tid] = b2[tid];
    if (tid < 128) sB3[tid] = b3[tid];

    // --- prologue: transpose this worker's slice (512 n-columns) ---
    {
        float (*tile)[33] = (float (*)[33])(sm + OFF_XT);
        int n0 = wl * 512;
        int txx = tid & 31, tyy = tid >> 5;   // tyy 0..15
        const float* src = pts + (size_t)b * CPn * Nn;
        float* dst = g_ptsT + (size_t)b * Nn * CPn;
        for (int ct = 0; ct < 2; ct++) {
            int c0 = ct * 32;
            for (int nt = 0; nt < 16; nt++) {
                int nn0 = n0 + nt * 32;
                tile[tyy][txx]      = src[(size_t)(c0 + tyy) * Nn + nn0 + txx];
                tile[tyy + 16][txx] = src[(size_t)(c0 + tyy + 16) * Nn + nn0 + txx];
                __syncthreads();
                dst[(size_t)(nn0 + tyy) * CPn + c0 + txx]      = tile[txx][tyy];
                dst[(size_t)(nn0 + tyy + 16) * CPn + c0 + txx] = tile[txx][tyy + 16];
                __syncthreads();
            }
        }
    }
    // --- prologue: candidate table slice (x,y,z,|p|^2) ---
    {
        int j = wl * 512 + tid;
        const float* xb = xyz + (size_t)b * Nn * 3;
        float x = xb[3 * j], y = xb[3 * j + 1], z = xb[3 * j + 2];
        g_spG[b * Nn + j] = make_float4(x, y, z, fmaf(z, z, fmaf(y, y, x * x)));
    }
    __syncthreads();

    int wid = tid >> 5, lane = tid & 31;
    int tx = tid & 63, ty = tid >> 6;
    int p0 = tx * 4;

    // --- per-point MLP: H3 (pre-bias layer3 acc) for own 512 points ---
    for (int sub = 0; sub < 2; sub++) {
        int jbase = wl * 512 + sub * 256;
        for (int p = wid; p < 256; p += 16) {
            int j = jbase + p;
            const float* pr = g_ptsT + ((size_t)(b * Nn + j)) * CPn;
            float v0 = (lane < 3) ? xyz[((size_t)(b * Nn + j)) * 3 + lane] : pr[lane - 3];
            sXt[lane * ST + p]        = v0;
            sXt[(lane + 32) * ST + p] = pr[lane + 29];
            if (lane < 3) sXt[(lane + 64) * ST + p] = pr[lane + 61];
        }
        __syncthreads();

        layer8<67, 64>(sXt, sW1t, sB1, sH1, p0, ty * 8);
        __syncthreads();
        layer8<64, 64>(sH1, sW2t, sB2, sH2, p0, ty * 8);
        __syncthreads();

        // layer 3: store raw per-point acc (bias/relu deferred to pooling)
        for (int pass = 0; pass < 2; pass++) {
            int o0 = ty * 8 + pass * 64;
            unsigned long long acc[4][4];
#pragma unroll
            for (int i = 0; i < 4; i++)
#pragma unroll
                for (int o = 0; o < 4; o++) acc[i][o] = pk2(0.0f, 0.0f);
            for (int c = 0; c < 64; c++) {
                float4 xv = *(const float4*)(sH2 + c * ST + p0);
                const ulonglong2* wp = (const ulonglong2*)(sW3t + c * 128 + o0);
                ulonglong2 wa = wp[0], wb = wp[1];
                unsigned long long xq[4] = {pk2(xv.x, xv.x), pk2(xv.y, xv.y),
                                            pk2(xv.z, xv.z), pk2(xv.w, xv.w)};
                unsigned long long wq[4] = {wa.x, wa.y, wb.x, wb.y};
#pragma unroll
                for (int i = 0; i < 4; i++)
#pragma unroll
                    for (int o = 0; o < 4; o++) fma2(acc[i][o], xq[i], wq[o]);
            }
#pragma unroll
            for (int i = 0; i < 4; i++) {
                size_t row = ((size_t)(b * Nn + jbase + p0 + i)) * C3n;
#pragma unroll
                for (int o = 0; o < 4; o++)
                    *(unsigned long long*)(g_H3 + row + o0 + 2 * o) = acc[i][o];
            }
        }
        __syncthreads();   // sH2 (=sXt) dead before next sub's gather
    }

    // publish H3 + tables; wait for all 8 workers of this batch
    __threadfence();
    __syncthreads();
    if (tid == 0) {
        atomicAdd(&g_tcount[b], 1u);
        while (acq_u32(&g_tcount[b]) < tbase + 8u) __nanosleep(128);
    }
    __syncthreads();

    // stage full candidate table once (H1 region is dead now)
    const float4* spb = g_spG + b * Nn;
#pragma unroll
    for (int i = 0; i < 8; i++) spS[tid + i * 512] = spb[tid + i * 512];
    __syncthreads();

    const float INF = __int_as_float(0x7f800000);
    const float* h3b = g_H3 + (size_t)b * Nn * C3n;

    for (int k = 0; k < 8; k++) {
        int chunk = wl + 8 * k;
        int s0 = chunk * 16;
        if (tid == 0) {
            while (acq_u32(&g_progress[b]) < pbase + (unsigned)(s0 + 16)) __nanosleep(128);
        }
        __syncthreads();

        int s = s0 + wid;   // this warp's centroid

        // ---- knn: warp-collective top-32 over the SMEM table ----
        {
            const float* cp = out_xyz + ((size_t)b * Sn + s) * 3;
            float nx = ldcg_f(cp), ny = ldcg_f(cp + 1), nz = ldcg_f(cp + 2);
            float cn = fmaf(nz, nz, fmaf(ny, ny, nx * nx));
            float cur_d = INF; int cur_i = 0x7fffffff;
            float wmax = INF;
            for (int j0 = 0; j0 < Nn; j0 += 32) {
                float4 p = spS[j0 + lane];
                float dot = fmaf(nz, p.z, fmaf(ny, p.y, nx * p.x));
                float d = (cn + p.w) - 2.0f * dot;
                unsigned mask = __ballot_sync(FULL, d <= wmax);
                while (mask) {
                    int src = __ffs(mask) - 1;
                    mask &= mask - 1;
                    float dn = __shfl_sync(FULL, d, src);
                    int   ix = j0 + src;
                    bool less = (cur_d < dn) || (cur_d == dn && cur_i < ix);
                    int pos = __popc(__ballot_sync(FULL, less));
                    if (pos < 32) {
                        float ud = __shfl_up_sync(FULL, cur_d, 1);
                        int   ui = __shfl_up_sync(FULL, cur_i, 1);
                        if (lane > pos)       { cur_d = ud; cur_i = ui; }
                        else if (lane == pos) { cur_d = dn; cur_i = ix; }
                        wmax = __shfl_sync(FULL, cur_d, 31);
                    }
                }
            }
            sknn[wid * 32 + lane] = cur_i;
        }
        __syncwarp();

        // ---- pooling: max over 32 neighbors' H3 rows, then bias+relu ----
        {
            int ch = lane * 4;
            float4 m = make_float4(-INF, -INF, -INF, -INF);
#pragma unroll 4
            for (int t = 0; t < 32; t++) {
                int j = sknn[wid * 32 + t];            // broadcast LDS
                float4 v = *(const float4*)(h3b + (size_t)j * C3n + ch);
                m.x = fmaxf(m.x, v.x); m.y = fmaxf(m.y, v.y);
                m.z = fmaxf(m.z, v.z); m.w = fmaxf(m.w, v.w);
            }
            float4 bb = *(const float4*)(sB3 + ch);
            float* ob = out_np + (size_t)b * C3n * Sn + s;
            ob[(size_t)(ch + 0) * Sn] = fmaxf(m.x + bb.x, 0.0f);
            ob[(size_t)(ch + 1) * Sn] = fmaxf(m.y + bb.y, 0.0f);
            ob[(size_t)(ch + 2) * Sn] = fmaxf(m.z + bb.z, 0.0f);
            ob[(size_t)(ch + 3) * Sn] = fmaxf(m.w + bb.w, 0.0f);
        }
        __syncthreads();   // sknn reused next chunk
    }
}

// ---------------------------------------------------------------------------
extern "C" void kernel_launch(void* const* d_in, const int* in_sizes, int n_in,
                              void* d_out, int out_size)
{
    (void)in_sizes; (void)n_in; (void)out_size;
    const float* xyz = (const float*)d_in[0];
    const float* pts = (const float*)d_in[1];
    const float* W1  = (const float*)d_in[2];
    const float* b1  = (const float*)d_in[3];
    const float* W2  = (const float*)d_in[4];
    const float* b2  = (const float*)d_in[5];
    const float* W3  = (const float*)d_in[6];
    const float* b3  = (const float*)d_in[7];

    float* out      = (float*)d_out;
    float* out_xyz  = out;                       // (B,S,3)
    float* out_np   = out + (size_t)Bn * Sn * 3; // (B,128,S)

    cudaFuncSetAttribute(sa_kernel, cudaFuncAttributeMaxDynamicSharedMemorySize, SMEM_BYTES);
    sa_kernel<<<NBLK, 512, SMEM_BYTES>>>(xyz, pts, W1, b1, W2, b2, W3, b3,
                                         out_xyz, out_np);
}

// round 10
// speedup vs baseline: 2.0348x; 2.0348x over previous
#include <cuda_runtime.h>

// Problem constants (fixed shapes per problem spec)
namespace {
constexpr int Bn  = 16;
constexpr int Nn  = 4096;
constexpr int Sn  = 1024;
constexpr int CPn = 64;   // point feature channels
constexpr int C3n = 128;  // final MLP out channels
constexpr int NBLK = 144; // 16 fps blocks + 128 worker blocks (<= 148 SMs)
}

// Persistent device scratch (no allocation). All sync counters are MONOTONE
// across launches/replays (never reset), so graph replay and ncu replay stay
// correct without initialization.
__device__ float    g_ptsT[(size_t)Bn * Nn * CPn];  // points (B,N,CP)
__device__ float4   g_spG[Bn * Nn];                 // (x,y,z,|p|^2) per point
__device__ float    g_H3[(size_t)Bn * Nn * C3n];    // per-point layer3 acc (pre-bias)
__device__ unsigned g_bar;                          // ticket barrier
__device__ unsigned g_progress[Bn];                 // fps centroids produced (multiples of 16)
__device__ unsigned g_tcount[Bn];                   // worker H3+tables done

// ---------------------------------------------------------------------------
// helpers
// ---------------------------------------------------------------------------
__device__ __forceinline__ unsigned long long pk2(float lo, float hi) {
    unsigned long long r;
    asm("mov.b64 %0, {%1, %2};" : "=l"(r) : "f"(lo), "f"(hi));
    return r;
}
__device__ __forceinline__ void fma2(unsigned long long& d,
                                     unsigned long long a, unsigned long long b) {
    asm("fma.rn.f32x2 %0, %1, %2, %0;" : "+l"(d) : "l"(a), "l"(b));
}
__device__ __forceinline__ unsigned long long fma2v(unsigned long long a,
                                                    unsigned long long b,
                                                    unsigned long long c) {
    unsigned long long d;
    asm("fma.rn.f32x2 %0, %1, %2, %3;" : "=l"(d) : "l"(a), "l"(b), "l"(c));
    return d;
}
__device__ __forceinline__ unsigned long long mul2(unsigned long long a,
                                                   unsigned long long b) {
    unsigned long long d;
    asm("mul.rn.f32x2 %0, %1, %2;" : "=l"(d) : "l"(a), "l"(b));
    return d;
}
__device__ __forceinline__ unsigned long long add2(unsigned long long a,
                                                   unsigned long long b) {
    unsigned long long d;
    asm("add.rn.f32x2 %0, %1, %2;" : "=l"(d) : "l"(a), "l"(b));
    return d;
}
__device__ __forceinline__ float2 up2(unsigned long long v) {
    float lo, hi;
    asm("mov.b64 {%0, %1}, %2;" : "=f"(lo), "=f"(hi) : "l"(v));
    return make_float2(lo, hi);
}
__device__ __forceinline__ unsigned acq_u32(const unsigned* p) {
    unsigned v;
    asm volatile("ld.global.acquire.gpu.u32 %0, [%1];" : "=r"(v) : "l"(p));
    return v;
}
__device__ __forceinline__ void rel_u32(unsigned* p, unsigned v) {
    asm volatile("st.global.release.gpu.u32 [%0], %1;" :: "l"(p), "r"(v) : "memory");
}
__device__ __forceinline__ float ldcg_f(const float* p) {
    float v;
    asm volatile("ld.global.cg.f32 %0, [%1];" : "=f"(v) : "l"(p));
    return v;
}

// ---------------------------------------------------------------------------
// Worker SMEM layout (floats):
//   W1t[67][64] W2t[64][64] W3t[64][128] b1 b2 b3 | knn idx (512 ints) |
//   Xt[67][ST]  H1[64][ST]
// H1 doubles as the staged kNN candidate table; Xt doubles as the pooled-
// output staging buffer (both dead in those phases).
// ---------------------------------------------------------------------------
constexpr int ST       = 260;
constexpr int OFF_W1T  = 0;
constexpr int OFF_W2T  = OFF_W1T + 67 * 64;
constexpr int OFF_W3T  = OFF_W2T + 64 * 64;
constexpr int OFF_B1   = OFF_W3T + 64 * 128;
constexpr int OFF_B2   = OFF_B1 + 64;
constexpr int OFF_B3   = OFF_B2 + 64;
constexpr int OFF_KNN  = OFF_B3 + 128;          // 512 ints
constexpr int OFF_XT   = OFF_KNN + 512;
constexpr int OFF_H1   = OFF_XT + 67 * ST;      // 16B-aligned
constexpr int SMEM_FLOATS = OFF_H1 + 64 * ST;
constexpr int SMEM_BYTES  = SMEM_FLOATS * 4;    // 205,616 B

// One dense layer tile for 512 threads: 4 points x 8 outs per thread.
template <int C, int WS>
__device__ __forceinline__ void layer8(const float* __restrict__ Xs,
                                       const float* __restrict__ Wt,
                                       const float* __restrict__ Bs,
                                       float* __restrict__ Hs,
                                       int p0, int o0)
{
    unsigned long long acc[4][4];
#pragma unroll
    for (int i = 0; i < 4; i++)
#pragma unroll
        for (int o = 0; o < 4; o++) acc[i][o] = pk2(0.0f, 0.0f);

    for (int c = 0; c < C; c++) {
        float4 xv = *(const float4*)(Xs + c * ST + p0);
        const ulonglong2* wp = (const ulonglong2*)(Wt + c * WS + o0);
        ulonglong2 wa = wp[0], wb = wp[1];
        unsigned long long xq[4] = {pk2(xv.x, xv.x), pk2(xv.y, xv.y),
                                    pk2(xv.z, xv.z), pk2(xv.w, xv.w)};
        unsigned long long wq[4] = {wa.x, wa.y, wb.x, wb.y};
#pragma unroll
        for (int i = 0; i < 4; i++)
#pragma unroll
            for (int o = 0; o < 4; o++) fma2(acc[i][o], xq[i], wq[o]);
    }
#pragma unroll
    for (int o = 0; o < 4; o++) {
        float b0 = Bs[o0 + 2 * o], b1 = Bs[o0 + 2 * o + 1];
        float2 a0 = up2(acc[0][o]), a1 = up2(acc[1][o]);
        float2 a2 = up2(acc[2][o]), a3 = up2(acc[3][o]);
        float4 ve = make_float4(fmaxf(a0.x + b0, 0.f), fmaxf(a1.x + b0, 0.f),
                                fmaxf(a2.x + b0, 0.f), fmaxf(a3.x + b0, 0.f));
        float4 vo = make_float4(fmaxf(a0.y + b1, 0.f), fmaxf(a1.y + b1, 0.f),
                                fmaxf(a2.y + b1, 0.f), fmaxf(a3.y + b1, 0.f));
        *(float4*)(Hs + (o0 + 2 * o) * ST + p0)     = ve;
        *(float4*)(Hs + (o0 + 2 * o + 1) * ST + p0) = vo;
    }
}

// ---------------------------------------------------------------------------
// The megakernel: blocks 0..15 = FPS producers, 16..143 = workers.
// ---------------------------------------------------------------------------
__global__ __launch_bounds__(512) void sa_kernel(
    const float* __restrict__ xyz, const float* __restrict__ pts,
    const float* __restrict__ W1, const float* __restrict__ b1,
    const float* __restrict__ W2, const float* __restrict__ b2,
    const float* __restrict__ W3, const float* __restrict__ b3,
    float* out_xyz, float* out_np)
{
    extern __shared__ float sm[];
    int bx = blockIdx.x;
    int tid = threadIdx.x;
    const unsigned FULL = 0xffffffffu;

    __shared__ unsigned s_base[2];

    // read monotone bases BEFORE the rendezvous, then ticket barrier over all
    // 144 co-resident blocks
    if (tid == 0) {
        int bb = (bx < 16) ? bx : ((bx - 16) >> 3);
        s_base[0] = acq_u32(&g_progress[bb]);
        s_base[1] = acq_u32(&g_tcount[bb]);
        unsigned ticket = atomicAdd(&g_bar, 1u);
        unsigned gen = ticket / NBLK;
        while (acq_u32(&g_bar) < (gen + 1) * NBLK) __nanosleep(64);
    }
    __syncthreads();
    unsigned pbase = s_base[0];

    if (bx < 16) {
        // =================== FPS producer ==================================
        float* sx = sm;
        float* sy = sm + Nn;
        float* sz = sm + 2 * Nn;
        unsigned* sdist = (unsigned*)(sm + 3 * Nn);
        unsigned* sidx  = sdist + 32;
        float* ring = (float*)(sidx + 32);      // 48 floats, 16B-aligned

        int b = bx, t = tid;
        const float* xb = xyz + (size_t)b * Nn * 3;

        unsigned long long px2[4], py2[4], pz2[4];
        float dist[8];
#pragma unroll
        for (int i = 0; i < 4; i++) {
            int j0 = t + (2 * i) * 512;
            int j1 = t + (2 * i + 1) * 512;
            float x0 = xb[3 * j0], y0 = xb[3 * j0 + 1], z0 = xb[3 * j0 + 2];
            float x1 = xb[3 * j1], y1 = xb[3 * j1 + 1], z1 = xb[3 * j1 + 2];
            px2[i] = pk2(x0, x1); py2[i] = pk2(y0, y1); pz2[i] = pk2(z0, z1);
            sx[j0] = x0; sy[j0] = y0; sz[j0] = z0;
            sx[j1] = x1; sy[j1] = y1; sz[j1] = z1;
            dist[2 * i] = 1e10f; dist[2 * i + 1] = 1e10f;
        }
        __syncthreads();

        float cx = sx[0], cy = sy[0], cz = sz[0];
        if (t == 0) { ring[0] = cx; ring[1] = cy; ring[2] = cz; }

        int lane = t & 31, wd = t >> 5;
        for (int it = 1; it < Sn; ++it) {
            unsigned long long ncx2 = pk2(-cx, -cx);
            unsigned long long ncy2 = pk2(-cy, -cy);
            unsigned long long ncz2 = pk2(-cz, -cz);
#pragma unroll
            for (int i = 0; i < 4; i++) {
                unsigned long long dx = add2(px2[i], ncx2);
                unsigned long long dy = add2(py2[i], ncy2);
                unsigned long long dz = add2(pz2[i], ncz2);
                unsigned long long d2 = mul2(dx, dx);
                d2 = fma2v(dy, dy, d2);
                d2 = fma2v(dz, dz, d2);
                float2 dd = up2(d2);
                dist[2 * i]     = fminf(dist[2 * i], dd.x);
                dist[2 * i + 1] = fminf(dist[2 * i + 1], dd.y);
            }
            float mv = fmaxf(fmaxf(fmaxf(dist[0], dist[1]), fmaxf(dist[2], dist[3])),
                             fmaxf(fmaxf(dist[4], dist[5]), fmaxf(dist[6], dist[7])));
            int mi = t;
#pragma unroll
            for (int s = 7; s >= 0; s--)
                if (dist[s] == mv) mi = t + s * 512;   // lowest index wins

            unsigned db = __float_as_uint(mv);
            unsigned wm = __reduce_max_sync(FULL, db);
            unsigned ci = (db == wm) ? (unsigned)mi : 0xffffffffu;
            unsigned wi = __reduce_min_sync(FULL, ci);
            int slot = (it & 1) * 16 + wd;
            if (lane == 0) { sdist[slot] = wm; sidx[slot] = wi; }
            __syncthreads();

            int rs = (it & 1) * 16 + (lane & 15);
            unsigned d16 = sdist[rs];
            unsigned i16 = sidx[rs];
            unsigned gm  = __reduce_max_sync(FULL, d16);
            unsigned gc  = (d16 == gm) ? i16 : 0xffffffffu;
            unsigned far = __reduce_min_sync(FULL, gc);
            cx = sx[far]; cy = sy[far]; cz = sz[far];
            if (t == 0) {
                int sl3 = (it & 15) * 3;
                ring[sl3] = cx; ring[sl3 + 1] = cy; ring[sl3 + 2] = cz;
                if ((it & 15) == 15) {
                    // publish 16 centroids (it-15 .. it): 12 float4 stores +
                    // one release (orders the stores before the progress bump)
                    float4* dst = (float4*)(out_xyz + ((size_t)b * Sn + (it - 15)) * 3);
                    const float4* srcv = (const float4*)ring;
#pragma unroll
                    for (int r = 0; r < 12; r++) dst[r] = srcv[r];
                    rel_u32(&g_progress[b], pbase + (unsigned)it + 1u);
                }
            }
        }
        return;
    }

    // ======================= worker ========================================
    int b  = (bx - 16) >> 3;
    int wl = (bx - 16) & 7;
    unsigned tbase = s_base[1];

    float* sW1t = sm + OFF_W1T;
    float* sW2t = sm + OFF_W2T;
    float* sW3t = sm + OFF_W3T;
    float* sB1  = sm + OFF_B1;
    float* sB2  = sm + OFF_B2;
    float* sB3  = sm + OFF_B3;
    int*   sknn = (int*)(sm + OFF_KNN);
    float* sXt  = sm + OFF_XT;
    float* sH1  = sm + OFF_H1;
    float* sH2  = sXt;
    float4* spS = (float4*)(sm + OFF_H1);   // staged candidate table (aliases H1)
    float* pool = sm + OFF_XT;              // pooled-output staging (aliases Xt)

    // --- prologue: weights to smem ---
    for (int i = tid; i < 64 * 67; i += 512) { int o = i / 67, c = i % 67; sW1t[c * 64 + o] = W1[i]; }
    for (int i = tid; i < 64 * 64; i += 512) { int o = i >> 6, c = i & 63; sW2t[c * 64 + o] = W2[i]; }
    for (int i = tid; i < 128 * 64; i += 512){ int o = i >> 6, c = i & 63; sW3t[c * 128 + o] = W3[i]; }
    if (tid < 64)  sB1[tid] = b1[tid];
    if (tid < 64)  sB2[tid] = b2[tid];
    if (tid < 128) sB3[tid] = b3[tid];

    // --- prologue: transpose this worker's slice (512 n-columns) ---
    {
        float (*tile)[33] = (float (*)[33])(sm + OFF_XT);
        int n0 = wl * 512;
        int txx = tid & 31, tyy = tid >> 5;   // tyy 0..15
        const float* src = pts + (size_t)b * CPn * Nn;
        float* dst = g_ptsT + (size_t)b * Nn * CPn;
        for (int ct = 0; ct < 2; ct++) {
            int c0 = ct * 32;
            for (int nt = 0; nt < 16; nt++) {
                int nn0 = n0 + nt * 32;
                tile[tyy][txx]      = src[(size_t)(c0 + tyy) * Nn + nn0 + txx];
                tile[tyy + 16][txx] = src[(size_t)(c0 + tyy + 16) * Nn + nn0 + txx];
                __syncthreads();
                dst[(size_t)(nn0 + tyy) * CPn + c0 + txx]      = tile[txx][tyy];
                dst[(size_t)(nn0 + tyy + 16) * CPn + c0 + txx] = tile[txx][tyy + 16];
                __syncthreads();
            }
        }
    }
    // --- prologue: candidate table slice (x,y,z,|p|^2) ---
    {
        int j = wl * 512 + tid;
        const float* xb = xyz + (size_t)b * Nn * 3;
        float x = xb[3 * j], y = xb[3 * j + 1], z = xb[3 * j + 2];
        g_spG[b * Nn + j] = make_float4(x, y, z, fmaf(z, z, fmaf(y, y, x * x)));
    }
    __syncthreads();

    int wid = tid >> 5, lane = tid & 31;
    int tx = tid & 63, ty = tid >> 6;
    int p0 = tx * 4;

    // --- per-point MLP: H3 (pre-bias layer3 acc) for own 512 points ---
    for (int sub = 0; sub < 2; sub++) {
        int jbase = wl * 512 + sub * 256;
        for (int p = wid; p < 256; p += 16) {
            int j = jbase + p;
            const float* pr = g_ptsT + ((size_t)(b * Nn + j)) * CPn;
            float v0 = (lane < 3) ? xyz[((size_t)(b * Nn + j)) * 3 + lane] : pr[lane - 3];
            sXt[lane * ST + p]        = v0;
            sXt[(lane + 32) * ST + p] = pr[lane + 29];
            if (lane < 3) sXt[(lane + 64) * ST + p] = pr[lane + 61];
        }
        __syncthreads();

        layer8<67, 64>(sXt, sW1t, sB1, sH1, p0, ty * 8);
        __syncthreads();
        layer8<64, 64>(sH1, sW2t, sB2, sH2, p0, ty * 8);
        __syncthreads();

        // layer 3: store raw per-point acc (bias/relu deferred to pooling)
        for (int pass = 0; pass < 2; pass++) {
            int o0 = ty * 8 + pass * 64;
            unsigned long long acc[4][4];
#pragma unroll
            for (int i = 0; i < 4; i++)
#pragma unroll
                for (int o = 0; o < 4; o++) acc[i][o] = pk2(0.0f, 0.0f);
            for (int c = 0; c < 64; c++) {
                float4 xv = *(const float4*)(sH2 + c * ST + p0);
                const ulonglong2* wp = (const ulonglong2*)(sW3t + c * 128 + o0);
                ulonglong2 wa = wp[0], wb = wp[1];
                unsigned long long xq[4] = {pk2(xv.x, xv.x), pk2(xv.y, xv.y),
                                            pk2(xv.z, xv.z), pk2(xv.w, xv.w)};
                unsigned long long wq[4] = {wa.x, wa.y, wb.x, wb.y};
#pragma unroll
                for (int i = 0; i < 4; i++)
#pragma unroll
                    for (int o = 0; o < 4; o++) fma2(acc[i][o], xq[i], wq[o]);
            }
#pragma unroll
            for (int i = 0; i < 4; i++) {
                size_t row = ((size_t)(b * Nn + jbase + p0 + i)) * C3n;
#pragma unroll
                for (int o = 0; o < 4; o++)
                    *(unsigned long long*)(g_H3 + row + o0 + 2 * o) = acc[i][o];
            }
        }
        __syncthreads();   // sH2 (=sXt) dead before next sub's gather
    }

    // publish H3 + tables; wait for all 8 workers of this batch
    __threadfence();
    __syncthreads();
    if (tid == 0) {
        atomicAdd(&g_tcount[b], 1u);
        while (acq_u32(&g_tcount[b]) < tbase + 8u) __nanosleep(256);
    }
    __syncthreads();

    // stage full candidate table once (H1 region is dead now)
    const float4* spb = g_spG + b * Nn;
#pragma unroll
    for (int i = 0; i < 8; i++) spS[tid + i * 512] = spb[tid + i * 512];
    __syncthreads();

    const float INF = __int_as_float(0x7f800000);
    const float* h3b = g_H3 + (size_t)b * Nn * C3n;

    for (int k = 0; k < 8; k++) {
        int chunk = wl + 8 * k;
        int s0 = chunk * 16;
        if (tid == 0) {
            while (acq_u32(&g_progress[b]) < pbase + (unsigned)(s0 + 16)) __nanosleep(256);
        }
        __syncthreads();

        int s = s0 + wid;   // this warp's centroid

        // ---- knn: warp-collective top-32 over the SMEM table ----
        {
            const float* cp = out_xyz + ((size_t)b * Sn + s) * 3;
            float nx = ldcg_f(cp), ny = ldcg_f(cp + 1), nz = ldcg_f(cp + 2);
            float cn = fmaf(nz, nz, fmaf(ny, ny, nx * nx));
            float cur_d = INF; int cur_i = 0x7fffffff;
            float wmax = INF;
            for (int j0 = 0; j0 < Nn; j0 += 32) {
                float4 p = spS[j0 + lane];
                float dot = fmaf(nz, p.z, fmaf(ny, p.y, nx * p.x));
                float d = (cn + p.w) - 2.0f * dot;
                unsigned mask = __ballot_sync(FULL, d <= wmax);
                while (mask) {
                    int src = __ffs(mask) - 1;
                    mask &= mask - 1;
                    float dn = __shfl_sync(FULL, d, src);
                    int   ix = j0 + src;
                    bool less = (cur_d < dn) || (cur_d == dn && cur_i < ix);
                    int pos = __popc(__ballot_sync(FULL, less));
                    if (pos < 32) {
                        float ud = __shfl_up_sync(FULL, cur_d, 1);
                        int   ui = __shfl_up_sync(FULL, cur_i, 1);
                        if (lane > pos)       { cur_d = ud; cur_i = ui; }
                        else if (lane == pos) { cur_d = dn; cur_i = ix; }
                        wmax = __shfl_sync(FULL, cur_d, 31);
                    }
                }
            }
            sknn[wid * 32 + lane] = cur_i;
        }
        __syncwarp();

        // ---- pooling: max over 32 neighbors' H3 rows, then bias+relu,
        //      staged in SMEM for coalesced output ----
        {
            int ch = lane * 4;
            float4 m = make_float4(-INF, -INF, -INF, -INF);
#pragma unroll 4
            for (int t = 0; t < 32; t++) {
                int j = sknn[wid * 32 + t];            // broadcast LDS
                float4 v = *(const float4*)(h3b + (size_t)j * C3n + ch);
                m.x = fmaxf(m.x, v.x); m.y = fmaxf(m.y, v.y);
                m.z = fmaxf(m.z, v.z); m.w = fmaxf(m.w, v.w);
            }
            float4 bb = *(const float4*)(sB3 + ch);
            float4 r = make_float4(fmaxf(m.x + bb.x, 0.0f), fmaxf(m.y + bb.y, 0.0f),
                                   fmaxf(m.z + bb.z, 0.0f), fmaxf(m.w + bb.w, 0.0f));
            *(float4*)(pool + wid * 132 + ch) = r;     // row stride 132 (pad)
        }
        __syncthreads();

        // coalesced write-out: lanes 0..15 cover consecutive centroids of one ch
        {
            float* ob = out_np + (size_t)b * C3n * Sn + s0;
#pragma unroll
            for (int i = 0; i < 4; i++) {
                int f  = i * 512 + tid;     // 0..2047
                int ch = f >> 4, sl = f & 15;
                ob[(size_t)ch * Sn + sl] = pool[sl * 132 + ch];
            }
        }
        __syncthreads();   // pool/sknn reused next chunk
    }
}

// ---------------------------------------------------------------------------
extern "C" void kernel_launch(void* const* d_in, const int* in_sizes, int n_in,
                              void* d_out, int out_size)
{
    (void)in_sizes; (void)n_in; (void)out_size;
    const float* xyz = (const float*)d_in[0];
    const float* pts = (const float*)d_in[1];
    const float* W1  = (const float*)d_in[2];
    const float* b1  = (const float*)d_in[3];
    const float* W2  = (const float*)d_in[4];
    const float* b2  = (const float*)d_in[5];
    const float* W3  = (const float*)d_in[6];
    const float* b3  = (const float*)d_in[7];

    float* out      = (float*)d_out;
    float* out_xyz  = out;                       // (B,S,3)
    float* out_np   = out + (size_t)Bn * Sn * 3; // (B,128,S)

    cudaFuncSetAttribute(sa_kernel, cudaFuncAttributeMaxDynamicSharedMemorySize, SMEM_BYTES);
    sa_kernel<<<NBLK, 512, SMEM_BYTES>>>(xyz, pts, W1, b1, W2, b2, W3, b3,
                                         out_xyz, out_np);
}